// round 15
// baseline (speedup 1.0000x reference)
#include <cuda_runtime.h>
#include <cuda_fp16.h>

// Output layout (flattened jax pytree, each region N*16 f32 = n4 float4s):
//   region 0: -x + tanh(agg)   region 1: x   region 2: -x
//   region 3: agg (f32, from fp16 accumulator)   region 4: tanh(agg)
//
// R15: pack kernel eliminated. The edge kernel's leading "producer" blocks
// copy regions 1/2 AND build g_x16 / zero g_agg16 (same x value, extra
// stores ~free), then signal a device flag; edge blocks spin on the flag.
// Safety: wave-1 capacity (~1184 blocks) < producerBlocks (1563) and blocks
// issue in bid order, so all producers schedule before any consumer spins.
// Flag is reset by final_kernel after its gridsync (edge complete); edge has
// NO PDL attr so it cannot overlap the previous final. Flag starts 0 and
// ends 0 every call -> deterministic and graph-capture-safe.

#define MAX_N 100000
__device__ uint4 g_x16[MAX_N * 2];    // fp16 copy of x: 32 B/node
__device__ uint4 g_agg16[MAX_N * 2];  // fp16 accumulators: 32 B/node
__device__ int   g_flag;              // producer done-counter (0 at rest)

__device__ __forceinline__ unsigned pack_h2(float a, float b) {
    __half2 h = __floats2half2_rn(a, b);
    return *reinterpret_cast<unsigned*>(&h);
}

__device__ __forceinline__ float2 h2f(unsigned u) {
    __half2 h = *reinterpret_cast<__half2*>(&u);
    return __half22float2(h);
}

__device__ __forceinline__ void msgs(float we, const uint4& ur, const uint4& uc,
                                     unsigned& p0, unsigned& p1,
                                     unsigned& p2, unsigned& p3) {
    float2 a0 = h2f(ur.x), a1 = h2f(ur.y), a2 = h2f(ur.z), a3 = h2f(ur.w);
    float2 b0 = h2f(uc.x), b1 = h2f(uc.y), b2 = h2f(uc.z), b3 = h2f(uc.w);
    p0 = pack_h2(we * __sinf(a0.x - b0.x), we * __sinf(a0.y - b0.y));
    p1 = pack_h2(we * __sinf(a1.x - b1.x), we * __sinf(a1.y - b1.y));
    p2 = pack_h2(we * __sinf(a2.x - b2.x), we * __sinf(a2.y - b2.y));
    p3 = pack_h2(we * __sinf(a3.x - b3.x), we * __sinf(a3.y - b3.y));
}

#define RED_V4F16X2(dst, p0, p1, p2, p3)                                    \
    asm volatile("red.global.add.noftz.v4.f16x2 [%0], {%1, %2, %3, %4};"    \
                 :: "l"(dst), "r"(p0), "r"(p1), "r"(p2), "r"(p3) : "memory")

__global__ void edge_kernel(const float4* __restrict__ x,
                            const int* __restrict__ row,
                            const int* __restrict__ col,
                            const float* __restrict__ w,
                            float4* __restrict__ out,
                            int n4, int n2, int E, int prodBlocks) {
    if (blockIdx.x < prodBlocks) {
        // Producer: regions 1/2 + fp16 pack + agg zero, then signal.
        int i = blockIdx.x * blockDim.x + threadIdx.x;
        if (i < n4) {
            float4 v = __ldg(&x[i]);
            __stcs(&out[n4 + i], v);                                      // region 1
            __stcs(&out[2 * n4 + i],
                   make_float4(-v.x, -v.y, -v.z, -v.w));                  // region 2
            ((uint2*)g_x16)[i] = make_uint2(pack_h2(v.x, v.y),
                                            pack_h2(v.z, v.w));
        }
        if (i < n2) g_agg16[i] = make_uint4(0u, 0u, 0u, 0u);
        __syncthreads();
        __threadfence();
        if (threadIdx.x == 0) atomicAdd(&g_flag, 1);
        return;
    }

    // Consumer: wait for all producers (acquire via atomic + fence).
    if (threadIdx.x == 0) {
        while (atomicAdd(&g_flag, 0) < prodBlocks) { }
    }
    __syncthreads();
    __threadfence();

    int t = (blockIdx.x - prodBlocks) * blockDim.x + threadIdx.x;
    int p = t >> 1;                  // pair index: edges p and p+Eh
    int h = t & 1;                   // lane-pair half: 8 dims each
    int Eh = (E + 1) >> 1;
    if (p >= Eh) return;
    int eB = p + Eh;
    bool hasB = eB < E;

    int   rA = __ldg(&row[p]);
    int   cA = __ldg(&col[p]);
    float wA = __ldg(&w[p]);
    int rB = rA, cB = cA; float wB = 0.f;
    if (hasB) { rB = __ldg(&row[eB]); cB = __ldg(&col[eB]); wB = __ldg(&w[eB]); }

    // Front-batch 4 independent 16 B gathers (MLP=4); lanes 2i/2i+1 of an
    // edge hit the same 32 B record -> 1 combined wavefront per endpoint.
    uint4 urA = __ldg(&g_x16[rA * 2 + h]);
    uint4 ucA = __ldg(&g_x16[cA * 2 + h]);
    uint4 urB = __ldg(&g_x16[rB * 2 + h]);
    uint4 ucB = __ldg(&g_x16[cB * 2 + h]);

    unsigned pa0, pa1, pa2, pa3, pb0, pb1, pb2, pb3;
    msgs(wA, urA, ucA, pa0, pa1, pa2, pa3);
    msgs(wB, urB, ucB, pb0, pb1, pb2, pb3);

    RED_V4F16X2(&g_agg16[cA * 2 + h], pa0, pa1, pa2, pa3);
    if (hasB) RED_V4F16X2(&g_agg16[cB * 2 + h], pb0, pb1, pb2, pb3);
}

// Final + PDL gridsync; also resets the flag for the next call/replay.
__global__ void final_kernel(const float4* __restrict__ x,
                             float4* __restrict__ out, int n4) {
    cudaGridDependencySynchronize();   // edge kernel fully complete
    if (blockIdx.x == 0 && threadIdx.x == 0) g_flag = 0;
    int i = blockIdx.x * blockDim.x + threadIdx.x;
    if (i >= n4) return;
    uint2 a16 = ((const uint2*)g_agg16)[i];     // 4 halves (L2-resident)
    float2 lo = h2f(a16.x), hi = h2f(a16.y);
    float4 a = make_float4(lo.x, lo.y, hi.x, hi.y);
    float4 v = __ldg(&x[i]);
    float4 t;
    t.x = tanhf(a.x); t.y = tanhf(a.y); t.z = tanhf(a.z); t.w = tanhf(a.w);
    __stcs(&out[3 * n4 + i], a);                                          // region 3
    __stcs(&out[4 * n4 + i], t);                                          // region 4
    __stcs(&out[i],
           make_float4(t.x - v.x, t.y - v.y, t.z - v.z, t.w - v.w));      // region 0
}

extern "C" void kernel_launch(void* const* d_in, const int* in_sizes, int n_in,
                              void* d_out, int out_size) {
    const float4* x   = (const float4*)d_in[0];
    const int*    row = (const int*)d_in[1];
    const int*    col = (const int*)d_in[2];
    const float*  w   = (const float*)d_in[3];

    int N  = in_sizes[0] / 16;   // 100000
    int E  = in_sizes[1];        // 3200000
    int n4 = N * 4;
    int n2 = N * 2;

    float4* out = (float4*)d_out;

    int Eh = (E + 1) >> 1;
    int edgeThreads = 2 * Eh;                  // 2 threads per edge-pair
    int edgeBlocks = (edgeThreads + 255) / 256;
    int prodBlocks = (n4 + 255) / 256;

    // Edge kernel: NO PDL (must fully follow previous final, which reads agg).
    edge_kernel<<<prodBlocks + edgeBlocks, 256>>>(x, row, col, w,
                                                  out, n4, n2, E, prodBlocks);

    // Final: PDL so its launch/prologue overlaps the edge tail.
    cudaLaunchAttribute pdl[1];
    pdl[0].id = cudaLaunchAttributeProgrammaticStreamSerialization;
    pdl[0].val.programmaticStreamSerializationAllowed = 1;
    cudaLaunchConfig_t cfg = {};
    cfg.gridDim  = dim3((n4 + 255) / 256);
    cfg.blockDim = dim3(256);
    cfg.stream   = 0;
    cfg.attrs    = pdl;
    cfg.numAttrs = 1;
    cudaLaunchKernelEx(&cfg, final_kernel, x, out, n4);
}

// round 16
// speedup vs baseline: 1.2260x; 1.2260x over previous
#include <cuda_runtime.h>
#include <cuda_fp16.h>

// Output layout (flattened jax pytree, each region N*16 f32 = n4 float4s):
//   region 0: -x + tanh(agg)   region 1: x   region 2: -x
//   region 3: agg (f32, from fp16 accumulator)   region 4: tanh(agg)
//
// R16 = R14 revert (best proven structure: PDL pack->edge->final, copy blocks
// overlap pack, ILP=2 edge) + micro-tweaks: early RED-A issue, pinned launch
// bounds, branchless B-edge for even E.

#define MAX_N 100000
__device__ uint4 g_x16[MAX_N * 2];    // fp16 copy of x: 32 B/node
__device__ uint4 g_agg16[MAX_N * 2];  // fp16 accumulators: 32 B/node

__device__ __forceinline__ unsigned pack_h2(float a, float b) {
    __half2 h = __floats2half2_rn(a, b);
    return *reinterpret_cast<unsigned*>(&h);
}

__device__ __forceinline__ float2 h2f(unsigned u) {
    __half2 h = *reinterpret_cast<__half2*>(&u);
    return __half22float2(h);
}

// Pack x -> fp16 and zero the fp16 accumulators (one pass).
__global__ void pack_kernel(const float4* __restrict__ x, int n4, int n2) {
    cudaTriggerProgrammaticLaunchCompletion();   // let edge grid start early
    int i = blockIdx.x * blockDim.x + threadIdx.x;
    if (i < n2) g_agg16[i] = make_uint4(0u, 0u, 0u, 0u);
    if (i >= n4) return;
    float4 v = __ldg(&x[i]);
    ((uint2*)g_x16)[i] = make_uint2(pack_h2(v.x, v.y), pack_h2(v.z, v.w));
}

__device__ __forceinline__ void msgs(float we, const uint4& ur, const uint4& uc,
                                     unsigned& p0, unsigned& p1,
                                     unsigned& p2, unsigned& p3) {
    float2 a0 = h2f(ur.x), a1 = h2f(ur.y), a2 = h2f(ur.z), a3 = h2f(ur.w);
    float2 b0 = h2f(uc.x), b1 = h2f(uc.y), b2 = h2f(uc.z), b3 = h2f(uc.w);
    p0 = pack_h2(we * __sinf(a0.x - b0.x), we * __sinf(a0.y - b0.y));
    p1 = pack_h2(we * __sinf(a1.x - b1.x), we * __sinf(a1.y - b1.y));
    p2 = pack_h2(we * __sinf(a2.x - b2.x), we * __sinf(a2.y - b2.y));
    p3 = pack_h2(we * __sinf(a3.x - b3.x), we * __sinf(a3.y - b3.y));
}

#define RED_V4F16X2(dst, p0, p1, p2, p3)                                    \
    asm volatile("red.global.add.noftz.v4.f16x2 [%0], {%1, %2, %3, %4};"    \
                 :: "l"(dst), "r"(p0), "r"(p1), "r"(p2), "r"(p3) : "memory")

// Copy blocks FIRST (no gridsync -> overlap pack); edge blocks gridsync,
// then 2 edges/thread, 2 threads/edge, lane-pair sector-combined gathers.
__global__ void __launch_bounds__(256, 8)
edge_copy_kernel(const float4* __restrict__ x,
                 const int* __restrict__ row,
                 const int* __restrict__ col,
                 const float* __restrict__ w,
                 float4* __restrict__ out,
                 int n4, int E, int copyBlocks) {
    if (blockIdx.x < copyBlocks) {
        int i = blockIdx.x * blockDim.x + threadIdx.x;
        if (i < n4) {
            float4 v = __ldg(&x[i]);
            __stcs(&out[n4 + i], v);                                      // region 1
            __stcs(&out[2 * n4 + i],
                   make_float4(-v.x, -v.y, -v.z, -v.w));                  // region 2
        }
        return;
    }

    cudaGridDependencySynchronize();   // pack's g_x16 / g_agg16 now visible

    int t = (blockIdx.x - copyBlocks) * blockDim.x + threadIdx.x;
    int p = t >> 1;                  // pair index: edges p and p+Eh
    int h = t & 1;                   // lane-pair half: 8 dims each
    int Eh = (E + 1) >> 1;
    if (p >= Eh) return;

    if ((E & 1) == 0) {              // compile-time-ish: E even -> B always valid
        int eB = p + Eh;
        int   rA = __ldg(&row[p]);
        int   cA = __ldg(&col[p]);
        float wA = __ldg(&w[p]);
        int   rB = __ldg(&row[eB]);
        int   cB = __ldg(&col[eB]);
        float wB = __ldg(&w[eB]);

        // Front-batch 4 independent 16 B gathers (MLP=4).
        uint4 urA = __ldg(&g_x16[rA * 2 + h]);
        uint4 ucA = __ldg(&g_x16[cA * 2 + h]);
        uint4 urB = __ldg(&g_x16[rB * 2 + h]);
        uint4 ucB = __ldg(&g_x16[cB * 2 + h]);

        unsigned pa0, pa1, pa2, pa3;
        msgs(wA, urA, ucA, pa0, pa1, pa2, pa3);
        RED_V4F16X2(&g_agg16[cA * 2 + h], pa0, pa1, pa2, pa3);  // early issue

        unsigned pb0, pb1, pb2, pb3;
        msgs(wB, urB, ucB, pb0, pb1, pb2, pb3);
        RED_V4F16X2(&g_agg16[cB * 2 + h], pb0, pb1, pb2, pb3);
    } else {
        int eB = p + Eh;
        bool hasB = eB < E;
        int   rA = __ldg(&row[p]);
        int   cA = __ldg(&col[p]);
        float wA = __ldg(&w[p]);
        int rB = rA, cB = cA; float wB = 0.f;
        if (hasB) { rB = __ldg(&row[eB]); cB = __ldg(&col[eB]); wB = __ldg(&w[eB]); }

        uint4 urA = __ldg(&g_x16[rA * 2 + h]);
        uint4 ucA = __ldg(&g_x16[cA * 2 + h]);
        uint4 urB = __ldg(&g_x16[rB * 2 + h]);
        uint4 ucB = __ldg(&g_x16[cB * 2 + h]);

        unsigned pa0, pa1, pa2, pa3;
        msgs(wA, urA, ucA, pa0, pa1, pa2, pa3);
        RED_V4F16X2(&g_agg16[cA * 2 + h], pa0, pa1, pa2, pa3);

        unsigned pb0, pb1, pb2, pb3;
        msgs(wB, urB, ucB, pb0, pb1, pb2, pb3);
        if (hasB) RED_V4F16X2(&g_agg16[cB * 2 + h], pb0, pb1, pb2, pb3);
    }
}

// Final (1 elem/thread) + gridsync so it PDL-overlaps the edge tail.
__global__ void final_kernel(const float4* __restrict__ x,
                             float4* __restrict__ out, int n4) {
    cudaGridDependencySynchronize();   // all REDs visible
    int i = blockIdx.x * blockDim.x + threadIdx.x;
    if (i >= n4) return;
    uint2 a16 = ((const uint2*)g_agg16)[i];     // 4 halves (L2-resident)
    float2 lo = h2f(a16.x), hi = h2f(a16.y);
    float4 a = make_float4(lo.x, lo.y, hi.x, hi.y);
    float4 v = __ldg(&x[i]);
    float4 t;
    t.x = tanhf(a.x); t.y = tanhf(a.y); t.z = tanhf(a.z); t.w = tanhf(a.w);
    __stcs(&out[3 * n4 + i], a);                                          // region 3
    __stcs(&out[4 * n4 + i], t);                                          // region 4
    __stcs(&out[i],
           make_float4(t.x - v.x, t.y - v.y, t.z - v.z, t.w - v.w));      // region 0
}

extern "C" void kernel_launch(void* const* d_in, const int* in_sizes, int n_in,
                              void* d_out, int out_size) {
    const float4* x   = (const float4*)d_in[0];
    const int*    row = (const int*)d_in[1];
    const int*    col = (const int*)d_in[2];
    const float*  w   = (const float*)d_in[3];

    int N  = in_sizes[0] / 16;   // 100000
    int E  = in_sizes[1];        // 3200000
    int n4 = N * 4;
    int n2 = N * 2;

    float4* out = (float4*)d_out;

    pack_kernel<<<(n4 + 255) / 256, 256>>>(x, n4, n2);

    cudaLaunchAttribute pdl[1];
    pdl[0].id = cudaLaunchAttributeProgrammaticStreamSerialization;
    pdl[0].val.programmaticStreamSerializationAllowed = 1;

    int Eh = (E + 1) >> 1;
    int edgeThreads = 2 * Eh;                  // 2 threads per edge-pair
    int edgeBlocks = (edgeThreads + 255) / 256;
    int copyBlocks = (n4 + 255) / 256;

    {
        cudaLaunchConfig_t cfg = {};
        cfg.gridDim  = dim3(copyBlocks + edgeBlocks);
        cfg.blockDim = dim3(256);
        cfg.stream   = 0;
        cfg.attrs    = pdl;
        cfg.numAttrs = 1;
        cudaLaunchKernelEx(&cfg, edge_copy_kernel,
                           x, row, col, w, out, n4, E, copyBlocks);
    }
    {
        cudaLaunchConfig_t cfg = {};
        cfg.gridDim  = dim3((n4 + 255) / 256);
        cfg.blockDim = dim3(256);
        cfg.stream   = 0;
        cfg.attrs    = pdl;
        cfg.numAttrs = 1;
        cudaLaunchKernelEx(&cfg, final_kernel, x, out, n4);
    }
}